// round 2
// baseline (speedup 1.0000x reference)
#include <cuda_runtime.h>
#include <cstdint>

// Problem dims (fixed for QuantizedLinear_49246095015985)
#define M_DIM 8192      // B*S = 4*2048
#define K_DIM 4096      // IN
#define N_DIM 4096      // OUT
#define KP    (K_DIM/4) // packed uint32 per row = 1024

// Scratch (device globals: allocation-free rule)
__device__ unsigned int g_Aq[(size_t)M_DIM * KP];   // 32 MB quantized activations (u8 packed)
__device__ unsigned int g_Wq[(size_t)N_DIM * KP];   // 16 MB packed weights (u8)
__device__ int g_rsA[M_DIM];                        // per-row sum of x_q
__device__ int g_rsW[N_DIM];                        // per-row sum of w_q

// ---------------------------------------------------------------------------
// Kernel 1: quantize activations. q = clip(rint(x/s) + zp, 0, 255), pack 4/word,
// and compute per-row sum of q. One block per row, 256 threads.
// ---------------------------------------------------------------------------
__global__ void quant_x_kernel(const float* __restrict__ x,
                               const float* __restrict__ act_scale,
                               const int* __restrict__ act_zp)
{
    const int row = blockIdx.x;
    const float s  = act_scale[0];
    const float zp = (float)act_zp[0];
    const float4* xr = reinterpret_cast<const float4*>(x + (size_t)row * K_DIM);

    unsigned int sum = 0;
    #pragma unroll
    for (int it = 0; it < KP / 256; ++it) {
        int w = threadIdx.x + it * 256;
        float4 v = xr[w];
        unsigned q0 = (unsigned)fminf(fmaxf(rintf(__fdiv_rn(v.x, s)) + zp, 0.f), 255.f);
        unsigned q1 = (unsigned)fminf(fmaxf(rintf(__fdiv_rn(v.y, s)) + zp, 0.f), 255.f);
        unsigned q2 = (unsigned)fminf(fmaxf(rintf(__fdiv_rn(v.z, s)) + zp, 0.f), 255.f);
        unsigned q3 = (unsigned)fminf(fmaxf(rintf(__fdiv_rn(v.w, s)) + zp, 0.f), 255.f);
        g_Aq[(size_t)row * KP + w] = q0 | (q1 << 8) | (q2 << 16) | (q3 << 24);
        sum += q0 + q1 + q2 + q3;
    }

    // block reduce (8 warps)
    #pragma unroll
    for (int off = 16; off > 0; off >>= 1)
        sum += __shfl_xor_sync(0xFFFFFFFFu, sum, off);
    __shared__ unsigned int wsum[8];
    if ((threadIdx.x & 31) == 0) wsum[threadIdx.x >> 5] = sum;
    __syncthreads();
    if (threadIdx.x == 0) {
        unsigned int t = 0;
        #pragma unroll
        for (int i = 0; i < 8; ++i) t += wsum[i];
        g_rsA[row] = (int)t;
    }
}

// ---------------------------------------------------------------------------
// Kernel 2: pack weights (int32 values 0..255) into u8 words + per-row sums.
// ---------------------------------------------------------------------------
__global__ void pack_w_kernel(const int* __restrict__ wq)
{
    const int row = blockIdx.x;
    const int4* wr = reinterpret_cast<const int4*>(wq + (size_t)row * K_DIM);

    unsigned int sum = 0;
    #pragma unroll
    for (int it = 0; it < KP / 256; ++it) {
        int w = threadIdx.x + it * 256;
        int4 v = wr[w];
        unsigned q0 = (unsigned)v.x, q1 = (unsigned)v.y, q2 = (unsigned)v.z, q3 = (unsigned)v.w;
        g_Wq[(size_t)row * KP + w] = q0 | (q1 << 8) | (q2 << 16) | (q3 << 24);
        sum += q0 + q1 + q2 + q3;
    }

    #pragma unroll
    for (int off = 16; off > 0; off >>= 1)
        sum += __shfl_xor_sync(0xFFFFFFFFu, sum, off);
    __shared__ unsigned int wsum[8];
    if ((threadIdx.x & 31) == 0) wsum[threadIdx.x >> 5] = sum;
    __syncthreads();
    if (threadIdx.x == 0) {
        unsigned int t = 0;
        #pragma unroll
        for (int i = 0; i < 8; ++i) t += wsum[i];
        g_rsW[row] = (int)t;
    }
}

// ---------------------------------------------------------------------------
// Kernel 3: u8 x u8 integer GEMM via dp4a + affine epilogue.
// Block tile 128x128, K-slab of 32 bytes (8 packed words), 256 threads,
// each thread computes an 8x8 micro-tile. Register prefetch of next tile.
// ---------------------------------------------------------------------------
__global__ __launch_bounds__(256, 2)
void gemm_u8_kernel(const float* __restrict__ wscale,
                    const int*   __restrict__ wzp,
                    const float* __restrict__ ascale,
                    const int*   __restrict__ azp,
                    const float* __restrict__ bias,
                    float*       __restrict__ out)
{
    __shared__ unsigned int As[8][128];  // [k-word][m]
    __shared__ unsigned int Bs[8][128];  // [k-word][n]

    const int tid  = threadIdx.x;
    const int lrow = tid >> 1;           // 0..127 tile row for loads
    const int lcol = (tid & 1) << 2;     // 0 or 4 (word offset within 8-word slab)
    const int tx   = tid & 15;           // 0..15 -> 8 output cols
    const int ty   = tid >> 4;           // 0..15 -> 8 output rows

    const unsigned int* Ag = g_Aq + (size_t)(blockIdx.y * 128 + lrow) * KP + lcol;
    const unsigned int* Bg = g_Wq + (size_t)(blockIdx.x * 128 + lrow) * KP + lcol;

    unsigned int acc[8][8];
    #pragma unroll
    for (int i = 0; i < 8; ++i)
        #pragma unroll
        for (int j = 0; j < 8; ++j) acc[i][j] = 0u;

    uint4 av = *reinterpret_cast<const uint4*>(Ag);
    uint4 bv = *reinterpret_cast<const uint4*>(Bg);

    for (int k0 = 0; k0 < KP; k0 += 8) {
        As[lcol + 0][lrow] = av.x; As[lcol + 1][lrow] = av.y;
        As[lcol + 2][lrow] = av.z; As[lcol + 3][lrow] = av.w;
        Bs[lcol + 0][lrow] = bv.x; Bs[lcol + 1][lrow] = bv.y;
        Bs[lcol + 2][lrow] = bv.z; Bs[lcol + 3][lrow] = bv.w;
        __syncthreads();

        if (k0 + 8 < KP) {  // prefetch next slab while computing
            av = *reinterpret_cast<const uint4*>(Ag + k0 + 8);
            bv = *reinterpret_cast<const uint4*>(Bg + k0 + 8);
        }

        #pragma unroll
        for (int kk = 0; kk < 8; ++kk) {
            uint4 a0 = *reinterpret_cast<const uint4*>(&As[kk][ty * 8]);
            uint4 a1 = *reinterpret_cast<const uint4*>(&As[kk][ty * 8 + 4]);
            uint4 b0 = *reinterpret_cast<const uint4*>(&Bs[kk][tx * 8]);
            uint4 b1 = *reinterpret_cast<const uint4*>(&Bs[kk][tx * 8 + 4]);
            unsigned int a[8] = {a0.x, a0.y, a0.z, a0.w, a1.x, a1.y, a1.z, a1.w};
            unsigned int b[8] = {b0.x, b0.y, b0.z, b0.w, b1.x, b1.y, b1.z, b1.w};
            #pragma unroll
            for (int i = 0; i < 8; ++i)
                #pragma unroll
                for (int j = 0; j < 8; ++j)
                    acc[i][j] = __dp4a(a[i], b[j], acc[i][j]);
        }
        __syncthreads();
    }

    // Epilogue: exact integer correction, then affine scale + bias.
    const float sa  = ascale[0];
    const long long zpa = (long long)azp[0];
    const int m0 = blockIdx.y * 128 + ty * 8;
    const int o0 = blockIdx.x * 128 + tx * 8;

    float ws[8]; float bi[8]; long long zw[8]; long long rw[8];
    #pragma unroll
    for (int j = 0; j < 8; ++j) {
        int o = o0 + j;
        ws[j] = wscale[o];
        bi[j] = bias[o];
        zw[j] = (long long)wzp[o];
        rw[j] = (long long)g_rsW[o];
    }

    #pragma unroll
    for (int i = 0; i < 8; ++i) {
        int m = m0 + i;
        long long ra = (long long)g_rsA[m];
        float* orow = out + (size_t)m * N_DIM + o0;
        #pragma unroll
        for (int j = 0; j < 8; ++j) {
            long long c = (long long)(int)acc[i][j]
                        - zw[j] * ra
                        - zpa * rw[j]
                        + (long long)K_DIM * zpa * zw[j];
            orow[j] = sa * ws[j] * (float)c + bi[j];
        }
    }
}

// ---------------------------------------------------------------------------
// Launch
// ---------------------------------------------------------------------------
extern "C" void kernel_launch(void* const* d_in, const int* in_sizes, int n_in,
                              void* d_out, int out_size)
{
    const float* x       = (const float*)d_in[0];
    const int*   wq      = (const int*)  d_in[1];
    const float* wscale  = (const float*)d_in[2];
    const int*   wzp     = (const int*)  d_in[3];
    const float* ascale  = (const float*)d_in[4];
    const int*   azp     = (const int*)  d_in[5];
    const float* bias    = (const float*)d_in[6];
    float*       out     = (float*)d_out;

    quant_x_kernel<<<M_DIM, 256>>>(x, ascale, azp);
    pack_w_kernel<<<N_DIM, 256>>>(wq);

    dim3 grid(N_DIM / 128, M_DIM / 128);
    gemm_u8_kernel<<<grid, 256>>>(wscale, wzp, ascale, azp, bias, out);
}

// round 6
// speedup vs baseline: 1.0647x; 1.0647x over previous
#include <cuda_runtime.h>
#include <cstdint>

// Problem dims (fixed for QuantizedLinear_49246095015985)
#define M_DIM 8192
#define K_DIM 4096
#define N_DIM 4096
#define KP    (K_DIM/4)

// GEMM tiling
#define BM 128
#define BN 128
#define BKB 64                  // K bytes per pipeline slab (2 mma k-steps of 32)
#define NST 4                   // pipeline stages
#define NIT (K_DIM / BKB)       // 64

#define STG_A (BM * BKB)        // 8192 B
#define STG_B (BN * BKB)        // 8192 B
#define OFF_A 0
#define OFF_B (NST * STG_A)                  // 32768
#define OFF_EPI (OFF_B + NST * STG_B)        // 65536
// epilogue arrays: tsc,tin,tzw,tbs (128 x f32/i32 each) + rsA(128)
#define SMEM_BYTES (OFF_EPI + 2560 + 1024)   // + align pad

// Scratch (device globals: allocation-free rule)
__device__ unsigned int g_Aq[(size_t)M_DIM * KP];   // 32 MB quantized activations
__device__ unsigned int g_Wq[(size_t)N_DIM * KP];   // 16 MB packed weights
__device__ int g_rsA[M_DIM];
__device__ int g_rsW[N_DIM];

// ---------------------------------------------------------------------------
// Helpers
// ---------------------------------------------------------------------------
__device__ __forceinline__ uint32_t cvta_smem(const void* p) {
    return (uint32_t)__cvta_generic_to_shared(p);
}

// row has 4 x 16B chunks (64B). XOR swizzle so 8 consecutive rows' chunks at a
// fixed logical chunk hit 8 distinct 16B positions within a 128B window.
__device__ __forceinline__ uint32_t swz(int row, int chunk) {
    return (uint32_t)(row * BKB + ((chunk ^ ((row >> 1) & 3)) << 4));
}

__device__ __forceinline__ void cp16(uint32_t dst, const void* src) {
    asm volatile("cp.async.cg.shared.global [%0], [%1], 16;\n" :: "r"(dst), "l"(src));
}
#define CP_COMMIT() asm volatile("cp.async.commit_group;" ::: "memory")
#define CP_WAIT(n)  asm volatile("cp.async.wait_group %0;" :: "n"(n) : "memory")

__device__ __forceinline__ void ldsm_x4(uint32_t (&r)[4], uint32_t addr) {
    asm volatile("ldmatrix.sync.aligned.m8n8.x4.shared.b16 {%0,%1,%2,%3}, [%4];"
                 : "=r"(r[0]), "=r"(r[1]), "=r"(r[2]), "=r"(r[3]) : "r"(addr));
}

__device__ __forceinline__ void mma_u8(int (&c)[4], const uint32_t (&a)[4],
                                       uint32_t b0, uint32_t b1) {
    asm volatile(
        "mma.sync.aligned.m16n8k32.row.col.s32.u8.u8.s32 "
        "{%0,%1,%2,%3}, {%4,%5,%6,%7}, {%8,%9}, {%0,%1,%2,%3};"
        : "+r"(c[0]), "+r"(c[1]), "+r"(c[2]), "+r"(c[3])
        : "r"(a[0]), "r"(a[1]), "r"(a[2]), "r"(a[3]), "r"(b0), "r"(b1));
}

// ---------------------------------------------------------------------------
// Kernel 1: quantize activations + per-row sums
// ---------------------------------------------------------------------------
__global__ void quant_x_kernel(const float* __restrict__ x,
                               const float* __restrict__ act_scale,
                               const int* __restrict__ act_zp)
{
    const int row = blockIdx.x;
    const float s  = act_scale[0];
    const float zp = (float)act_zp[0];
    const float4* xr = reinterpret_cast<const float4*>(x + (size_t)row * K_DIM);

    unsigned int sum = 0;
    #pragma unroll
    for (int it = 0; it < KP / 256; ++it) {
        int w = threadIdx.x + it * 256;
        float4 v = xr[w];
        unsigned q0 = (unsigned)fminf(fmaxf(rintf(__fdiv_rn(v.x, s)) + zp, 0.f), 255.f);
        unsigned q1 = (unsigned)fminf(fmaxf(rintf(__fdiv_rn(v.y, s)) + zp, 0.f), 255.f);
        unsigned q2 = (unsigned)fminf(fmaxf(rintf(__fdiv_rn(v.z, s)) + zp, 0.f), 255.f);
        unsigned q3 = (unsigned)fminf(fmaxf(rintf(__fdiv_rn(v.w, s)) + zp, 0.f), 255.f);
        g_Aq[(size_t)row * KP + w] = q0 | (q1 << 8) | (q2 << 16) | (q3 << 24);
        sum += q0 + q1 + q2 + q3;
    }

    #pragma unroll
    for (int off = 16; off > 0; off >>= 1)
        sum += __shfl_xor_sync(0xFFFFFFFFu, sum, off);
    __shared__ unsigned int wsum[8];
    if ((threadIdx.x & 31) == 0) wsum[threadIdx.x >> 5] = sum;
    __syncthreads();
    if (threadIdx.x == 0) {
        unsigned int t = 0;
        #pragma unroll
        for (int i = 0; i < 8; ++i) t += wsum[i];
        g_rsA[row] = (int)t;
    }
}

// ---------------------------------------------------------------------------
// Kernel 2: pack weights + per-row sums
// ---------------------------------------------------------------------------
__global__ void pack_w_kernel(const int* __restrict__ wq)
{
    const int row = blockIdx.x;
    const int4* wr = reinterpret_cast<const int4*>(wq + (size_t)row * K_DIM);

    unsigned int sum = 0;
    #pragma unroll
    for (int it = 0; it < KP / 256; ++it) {
        int w = threadIdx.x + it * 256;
        int4 v = wr[w];
        unsigned q0 = (unsigned)v.x, q1 = (unsigned)v.y, q2 = (unsigned)v.z, q3 = (unsigned)v.w;
        g_Wq[(size_t)row * KP + w] = q0 | (q1 << 8) | (q2 << 16) | (q3 << 24);
        sum += q0 + q1 + q2 + q3;
    }

    #pragma unroll
    for (int off = 16; off > 0; off >>= 1)
        sum += __shfl_xor_sync(0xFFFFFFFFu, sum, off);
    __shared__ unsigned int wsum[8];
    if ((threadIdx.x & 31) == 0) wsum[threadIdx.x >> 5] = sum;
    __syncthreads();
    if (threadIdx.x == 0) {
        unsigned int t = 0;
        #pragma unroll
        for (int i = 0; i < 8; ++i) t += wsum[i];
        g_rsW[row] = (int)t;
    }
}

// ---------------------------------------------------------------------------
// Kernel 3: IMMA GEMM via mma.sync.m16n8k32.u8.u8.s32.
// 128x128 CTA tile, 8 warps (4x2), warp tile 32x64, 4-stage cp.async ring.
// ---------------------------------------------------------------------------
__global__ __launch_bounds__(256, 2)
void gemm_imma_kernel(const float* __restrict__ wscale,
                      const int*   __restrict__ wzp,
                      const float* __restrict__ ascale,
                      const int*   __restrict__ azp,
                      const float* __restrict__ bias,
                      float*       __restrict__ out)
{
    extern __shared__ __align__(1024) uint8_t smem_raw[];
    uint32_t raw = cvta_smem(smem_raw);
    uint32_t sbase = (raw + 1023u) & ~1023u;
    uint8_t* smem_gen = smem_raw + (sbase - raw);

    const int tid = threadIdx.x;
    const int wid = tid >> 5;
    const int lid = tid & 31;
    const int wm  = wid & 3;        // warp row (32 rows each)
    const int wn  = wid >> 2;       // warp col (64 cols each)
    const int tile_m = blockIdx.y << 7;
    const int tile_n = blockIdx.x << 7;

    // Epilogue constants into smem
    float* tsc = reinterpret_cast<float*>(smem_gen + OFF_EPI);
    int*   tin = reinterpret_cast<int*>(smem_gen + OFF_EPI + 512);
    int*   tzw = reinterpret_cast<int*>(smem_gen + OFF_EPI + 1024);
    float* tbs = reinterpret_cast<float*>(smem_gen + OFF_EPI + 1536);
    int*   trA = reinterpret_cast<int*>(smem_gen + OFF_EPI + 2048);
    if (tid < 128) {
        const float sa = ascale[0];
        const int zpa = azp[0];
        int o = tile_n + tid;
        int zw = wzp[o];
        tzw[tid] = zw;
        tin[tid] = -zpa * (g_rsW[o] - K_DIM * zw);
        tsc[tid] = sa * wscale[o];
        tbs[tid] = bias[o];
        trA[tid] = g_rsA[tile_m + tid];
    }

    const uint8_t* Ab = reinterpret_cast<const uint8_t*>(g_Aq) + (size_t)tile_m * K_DIM;
    const uint8_t* Bb = reinterpret_cast<const uint8_t*>(g_Wq) + (size_t)tile_n * K_DIM;

    // stage loader: 512 chunks of 16B per matrix per stage, 2 per thread each
    auto load_stage = [&](int buf, int k0) {
        uint32_t aS = sbase + OFF_A + buf * STG_A;
        uint32_t bS = sbase + OFF_B + buf * STG_B;
        #pragma unroll
        for (int i = 0; i < 2; ++i) {
            int idx = tid + (i << 8);
            int r = idx >> 2, c = idx & 3;
            size_t go = (size_t)r * K_DIM + k0 + (c << 4);
            cp16(aS + swz(r, c), Ab + go);
            cp16(bS + swz(r, c), Bb + go);
        }
    };

    int acc[2][8][4];
    #pragma unroll
    for (int mt = 0; mt < 2; ++mt)
        #pragma unroll
        for (int nt = 0; nt < 8; ++nt)
            #pragma unroll
            for (int q = 0; q < 4; ++q) acc[mt][nt][q] = 0;

    // prologue: 3 stages in flight
    #pragma unroll
    for (int s = 0; s < NST - 1; ++s) { load_stage(s, s * BKB); CP_COMMIT(); }

    // precomputed ldmatrix lane geometry
    const int a_row = (lid & 7) + ((lid >> 3) & 1) * 8;   // within m16 tile
    const int a_ch  = (lid >> 4);                          // 0/1
    const int b_row = (lid & 7) + (lid >> 4) * 8;          // within n16 block
    const int b_ch  = ((lid >> 3) & 1);                    // 0/1

    for (int it = 0; it < NIT; ++it) {
        CP_WAIT(NST - 2);
        __syncthreads();

        int buf = it & (NST - 1);
        uint32_t aS = sbase + OFF_A + buf * STG_A;
        uint32_t bS = sbase + OFF_B + buf * STG_B;

        #pragma unroll
        for (int ks = 0; ks < 2; ++ks) {
            const int cb = ks << 1;
            uint32_t a[2][4];
            #pragma unroll
            for (int mt = 0; mt < 2; ++mt)
                ldsm_x4(a[mt], aS + swz(wm * 32 + mt * 16 + a_row, cb + a_ch));
            uint32_t b[8][2];
            #pragma unroll
            for (int b4 = 0; b4 < 4; ++b4) {
                uint32_t r4[4];
                ldsm_x4(r4, bS + swz(wn * 64 + b4 * 16 + b_row, cb + b_ch));
                b[2*b4][0] = r4[0]; b[2*b4][1] = r4[1];
                b[2*b4+1][0] = r4[2]; b[2*b4+1][1] = r4[3];
            }
            #pragma unroll
            for (int mt = 0; mt < 2; ++mt)
                #pragma unroll
                for (int nt = 0; nt < 8; ++nt)
                    mma_u8(acc[mt][nt], a[mt], b[nt][0], b[nt][1]);
        }

        __syncthreads();
        int nx = it + NST - 1;
        if (nx < NIT) load_stage(nx & (NST - 1), nx * BKB);
        CP_COMMIT();
    }

    // ---------------- Epilogue: integer correction + affine + bias ----------
    const int qrow = lid >> 2;
    const int qcol = (lid & 3) << 1;
    #pragma unroll
    for (int mt = 0; mt < 2; ++mt) {
        const int ml0 = wm * 32 + mt * 16 + qrow;     // local m, rows ml0, ml0+8
        const int ra0 = trA[ml0];
        const int ra1 = trA[ml0 + 8];
        float* orow0 = out + (size_t)(tile_m + ml0) * N_DIM + tile_n;
        float* orow1 = orow0 + (size_t)8 * N_DIM;
        #pragma unroll
        for (int nt = 0; nt < 8; ++nt) {
            const int nl = wn * 64 + nt * 8 + qcol;   // local n (pair nl, nl+1)
            const int z0 = tzw[nl], z1 = tzw[nl + 1];
            const int i0 = tin[nl], i1 = tin[nl + 1];
            const float s0 = tsc[nl], s1 = tsc[nl + 1];
            const float g0 = tbs[nl], g1 = tbs[nl + 1];
            float2 v0, v1;
            v0.x = s0 * (float)(acc[mt][nt][0] - z0 * ra0 + i0) + g0;
            v0.y = s1 * (float)(acc[mt][nt][1] - z1 * ra0 + i1) + g1;
            v1.x = s0 * (float)(acc[mt][nt][2] - z0 * ra1 + i0) + g0;
            v1.y = s1 * (float)(acc[mt][nt][3] - z1 * ra1 + i1) + g1;
            *reinterpret_cast<float2*>(orow0 + nl) = v0;
            *reinterpret_cast<float2*>(orow1 + nl) = v1;
        }
    }
}

// ---------------------------------------------------------------------------
// Launch
// ---------------------------------------------------------------------------
extern "C" void kernel_launch(void* const* d_in, const int* in_sizes, int n_in,
                              void* d_out, int out_size)
{
    const float* x       = (const float*)d_in[0];
    const int*   wq      = (const int*)  d_in[1];
    const float* wscale  = (const float*)d_in[2];
    const int*   wzp     = (const int*)  d_in[3];
    const float* ascale  = (const float*)d_in[4];
    const int*   azp     = (const int*)  d_in[5];
    const float* bias    = (const float*)d_in[6];
    float*       out     = (float*)d_out;

    cudaFuncSetAttribute(gemm_imma_kernel,
                         cudaFuncAttributeMaxDynamicSharedMemorySize, SMEM_BYTES);

    quant_x_kernel<<<M_DIM, 256>>>(x, ascale, azp);
    pack_w_kernel<<<N_DIM, 256>>>(wq);

    dim3 grid(N_DIM / BN, M_DIM / BM);   // (32, 64)
    gemm_imma_kernel<<<grid, 256, SMEM_BYTES>>>(wscale, wzp, ascale, azp, bias, out);
}

// round 7
// speedup vs baseline: 1.0668x; 1.0020x over previous
#include <cuda_runtime.h>
#include <cstdint>

// Problem dims (fixed for QuantizedLinear_49246095015985)
#define M_DIM 8192
#define K_DIM 4096
#define N_DIM 4096
#define KP    (K_DIM/4)

// GEMM tiling
#define BM 128
#define BN 128
#define BKB 64                  // K bytes per pipeline slab (2 mma k-steps of 32)
#define NST 4                   // pipeline stages
#define NIT (K_DIM / BKB)       // 64 k-slabs

#define SLAB 8192               // bytes per (tile, kslab) block = 128 rows x 64 B
#define STG_A SLAB
#define STG_B SLAB
#define OFF_A 0
#define OFF_B (NST * STG_A)                  // 32768
#define OFF_EPI (OFF_B + NST * STG_B)        // 65536
#define OFF_MB (OFF_EPI + 2560)              // 4 x 8B full barriers
#define SMEM_BYTES (OFF_MB + 64 + 1024)      // + align pad

// Scratch (device globals: allocation-free rule).
// TILED + PRE-SWIZZLED layout: g_Aq = [64 mtiles][64 kslabs][8KB swizzled block]
//                              g_Wq = [32 ntiles][64 kslabs][8KB swizzled block]
__device__ unsigned int g_Aq[(size_t)M_DIM * KP];   // 32 MB
__device__ unsigned int g_Wq[(size_t)N_DIM * KP];   // 16 MB
__device__ int g_rsA[M_DIM];
__device__ int g_rsW[N_DIM];

// ---------------------------------------------------------------------------
// Helpers
// ---------------------------------------------------------------------------
__device__ __forceinline__ uint32_t cvta_smem(const void* p) {
    return (uint32_t)__cvta_generic_to_shared(p);
}

// Within an 8KB block: row has 4 x 16B chunks (64B); XOR-swizzled chunk position.
__device__ __forceinline__ uint32_t swz(int row, int chunk) {
    return (uint32_t)(row * BKB + ((chunk ^ ((row >> 1) & 3)) << 4));
}

#define MBAR_INIT(addr, cnt) \
    asm volatile("mbarrier.init.shared.b64 [%0], %1;" :: "r"(addr), "r"(cnt) : "memory")

#define MBAR_EXPECT_TX(addr, bytes) \
    asm volatile("mbarrier.arrive.expect_tx.shared.b64 _, [%0], %1;" \
                 :: "r"(addr), "r"(bytes) : "memory")

#define MB_WAIT(addr, ph) do { \
    uint32_t _d_; \
    asm volatile("{\n\t.reg .pred p;\n\t" \
        "mbarrier.try_wait.parity.acquire.cta.shared::cta.b64 p, [%1], %2;\n\t" \
        "selp.b32 %0, 1, 0, p;\n\t}" : "=r"(_d_) : "r"(addr), "r"(ph) : "memory"); \
    while (!_d_) { \
        asm volatile("{\n\t.reg .pred p;\n\t" \
            "mbarrier.try_wait.parity.acquire.cta.shared::cta.b64 p, [%1], %2, 0x989680;\n\t" \
            "selp.b32 %0, 1, 0, p;\n\t}" : "=r"(_d_) : "r"(addr), "r"(ph) : "memory"); \
    } \
} while (0)

__device__ __forceinline__ void bulk_cp(uint32_t dst, const void* src,
                                        uint32_t bytes, uint32_t mbar) {
    asm volatile(
        "cp.async.bulk.shared::cluster.global.mbarrier::complete_tx::bytes "
        "[%0], [%1], %2, [%3];"
        :: "r"(dst), "l"(src), "r"(bytes), "r"(mbar) : "memory");
}

__device__ __forceinline__ void ldsm_x4(uint32_t (&r)[4], uint32_t addr) {
    asm volatile("ldmatrix.sync.aligned.m8n8.x4.shared.b16 {%0,%1,%2,%3}, [%4];"
                 : "=r"(r[0]), "=r"(r[1]), "=r"(r[2]), "=r"(r[3]) : "r"(addr));
}

__device__ __forceinline__ void mma_u8(int (&c)[4], const uint32_t (&a)[4],
                                       uint32_t b0, uint32_t b1) {
    asm volatile(
        "mma.sync.aligned.m16n8k32.row.col.s32.u8.u8.s32 "
        "{%0,%1,%2,%3}, {%4,%5,%6,%7}, {%8,%9}, {%0,%1,%2,%3};"
        : "+r"(c[0]), "+r"(c[1]), "+r"(c[2]), "+r"(c[3])
        : "r"(a[0]), "r"(a[1]), "r"(a[2]), "r"(a[3]), "r"(b0), "r"(b1));
}

// Destination word index in the tiled+swizzled layout for (tile row r in 0..127,
// word w in 0..1023 of the row), block base in words supplied by caller.
__device__ __forceinline__ uint32_t tiled_word(int r, int w) {
    int chunk  = (w >> 2) & 3;          // 16B chunk within 64B slab-row
    int within = w & 3;                 // word within 16B
    return (uint32_t)(r * 16 + ((chunk ^ ((r >> 1) & 3)) << 2) + within);
}

// ---------------------------------------------------------------------------
// Kernel 1: quantize activations + per-row sums, write tiled+swizzled layout
// ---------------------------------------------------------------------------
__global__ void quant_x_kernel(const float* __restrict__ x,
                               const float* __restrict__ act_scale,
                               const int* __restrict__ act_zp)
{
    const int row = blockIdx.x;
    const int mtile = row >> 7, r = row & 127;
    const float s  = act_scale[0];
    const float zp = (float)act_zp[0];
    const float4* xr = reinterpret_cast<const float4*>(x + (size_t)row * K_DIM);

    unsigned int sum = 0;
    #pragma unroll
    for (int it = 0; it < KP / 256; ++it) {
        int w = threadIdx.x + it * 256;
        float4 v = xr[w];
        unsigned q0 = (unsigned)fminf(fmaxf(rintf(__fdiv_rn(v.x, s)) + zp, 0.f), 255.f);
        unsigned q1 = (unsigned)fminf(fmaxf(rintf(__fdiv_rn(v.y, s)) + zp, 0.f), 255.f);
        unsigned q2 = (unsigned)fminf(fmaxf(rintf(__fdiv_rn(v.z, s)) + zp, 0.f), 255.f);
        unsigned q3 = (unsigned)fminf(fmaxf(rintf(__fdiv_rn(v.w, s)) + zp, 0.f), 255.f);
        int kslab = w >> 4;
        size_t base = ((size_t)(mtile * NIT + kslab)) * 2048;   // words per 8KB block
        g_Aq[base + tiled_word(r, w)] = q0 | (q1 << 8) | (q2 << 16) | (q3 << 24);
        sum += q0 + q1 + q2 + q3;
    }

    #pragma unroll
    for (int off = 16; off > 0; off >>= 1)
        sum += __shfl_xor_sync(0xFFFFFFFFu, sum, off);
    __shared__ unsigned int wsum[8];
    if ((threadIdx.x & 31) == 0) wsum[threadIdx.x >> 5] = sum;
    __syncthreads();
    if (threadIdx.x == 0) {
        unsigned int t = 0;
        #pragma unroll
        for (int i = 0; i < 8; ++i) t += wsum[i];
        g_rsA[row] = (int)t;
    }
}

// ---------------------------------------------------------------------------
// Kernel 2: pack weights + per-row sums, write tiled+swizzled layout
// ---------------------------------------------------------------------------
__global__ void pack_w_kernel(const int* __restrict__ wq)
{
    const int row = blockIdx.x;
    const int ntile = row >> 7, r = row & 127;
    const int4* wr = reinterpret_cast<const int4*>(wq + (size_t)row * K_DIM);

    unsigned int sum = 0;
    #pragma unroll
    for (int it = 0; it < KP / 256; ++it) {
        int w = threadIdx.x + it * 256;
        int4 v = wr[w];
        unsigned q0 = (unsigned)v.x, q1 = (unsigned)v.y, q2 = (unsigned)v.z, q3 = (unsigned)v.w;
        int kslab = w >> 4;
        size_t base = ((size_t)(ntile * NIT + kslab)) * 2048;
        g_Wq[base + tiled_word(r, w)] = q0 | (q1 << 8) | (q2 << 16) | (q3 << 24);
        sum += q0 + q1 + q2 + q3;
    }

    #pragma unroll
    for (int off = 16; off > 0; off >>= 1)
        sum += __shfl_xor_sync(0xFFFFFFFFu, sum, off);
    __shared__ unsigned int wsum[8];
    if ((threadIdx.x & 31) == 0) wsum[threadIdx.x >> 5] = sum;
    __syncthreads();
    if (threadIdx.x == 0) {
        unsigned int t = 0;
        #pragma unroll
        for (int i = 0; i < 8; ++i) t += wsum[i];
        g_rsW[row] = (int)t;
    }
}

// ---------------------------------------------------------------------------
// Kernel 3: IMMA GEMM, 128x128 CTA tile, 8 warps (4x2), warp tile 32x64.
// 4-stage ring fed by cp.async.bulk (one 8KB copy per matrix per stage,
// single issuing thread, mbarrier complete_tx).
// ---------------------------------------------------------------------------
__global__ __launch_bounds__(256, 2)
void gemm_imma_kernel(const float* __restrict__ wscale,
                      const int*   __restrict__ wzp,
                      const float* __restrict__ ascale,
                      const int*   __restrict__ azp,
                      const float* __restrict__ bias,
                      float*       __restrict__ out)
{
    extern __shared__ __align__(1024) uint8_t smem_raw[];
    uint32_t raw = cvta_smem(smem_raw);
    uint32_t sbase = (raw + 1023u) & ~1023u;
    uint8_t* smem_gen = smem_raw + (sbase - raw);

    const int tid = threadIdx.x;
    const int wid = tid >> 5;
    const int lid = tid & 31;
    const int wm  = wid & 3;        // warp row (32 rows each)
    const int wn  = wid >> 2;       // warp col (64 cols each)
    const int tile_m = blockIdx.y << 7;
    const int tile_n = blockIdx.x << 7;

    const uint8_t* Abase = reinterpret_cast<const uint8_t*>(g_Aq)
                         + (size_t)blockIdx.y * NIT * SLAB;
    const uint8_t* Bbase = reinterpret_cast<const uint8_t*>(g_Wq)
                         + (size_t)blockIdx.x * NIT * SLAB;
    const uint32_t mbf = sbase + OFF_MB;

    // Init barriers
    if (tid == 0) {
        #pragma unroll
        for (int s = 0; s < NST; ++s) MBAR_INIT(mbf + s * 8, 1);
        asm volatile("fence.proxy.async.shared::cta;" ::: "memory");
    }

    // Epilogue constants into smem
    float* tsc = reinterpret_cast<float*>(smem_gen + OFF_EPI);
    int*   tin = reinterpret_cast<int*>(smem_gen + OFF_EPI + 512);
    int*   tzw = reinterpret_cast<int*>(smem_gen + OFF_EPI + 1024);
    float* tbs = reinterpret_cast<float*>(smem_gen + OFF_EPI + 1536);
    int*   trA = reinterpret_cast<int*>(smem_gen + OFF_EPI + 2048);
    if (tid >= 128) {
        const float sa = ascale[0];
        const int zpa = azp[0];
        int n = tid - 128;
        int o = tile_n + n;
        int zw = wzp[o];
        tzw[n] = zw;
        tin[n] = -zpa * (g_rsW[o] - K_DIM * zw);
        tsc[n] = sa * wscale[o];
        tbs[n] = bias[o];
        trA[n] = g_rsA[tile_m + n];
    }
    __syncthreads();

    // Prologue: fill NST-1 stages
    if (tid == 0) {
        #pragma unroll
        for (int s = 0; s < NST - 1; ++s) {
            MBAR_EXPECT_TX(mbf + s * 8, 2 * SLAB);
            bulk_cp(sbase + OFF_A + s * STG_A, Abase + (size_t)s * SLAB, SLAB, mbf + s * 8);
            bulk_cp(sbase + OFF_B + s * STG_B, Bbase + (size_t)s * SLAB, SLAB, mbf + s * 8);
        }
    }

    int acc[2][8][4];
    #pragma unroll
    for (int mt = 0; mt < 2; ++mt)
        #pragma unroll
        for (int nt = 0; nt < 8; ++nt)
            #pragma unroll
            for (int q = 0; q < 4; ++q) acc[mt][nt][q] = 0;

    // ldmatrix lane geometry
    const int a_row = (lid & 7) + ((lid >> 3) & 1) * 8;
    const int a_ch  = (lid >> 4);
    const int b_row = (lid & 7) + (lid >> 4) * 8;
    const int b_ch  = ((lid >> 3) & 1);

    int pf[NST] = {0, 0, 0, 0};

    for (int it = 0; it < NIT; ++it) {
        int buf = it & (NST - 1);
        MB_WAIT(mbf + buf * 8, pf[buf]); pf[buf] ^= 1;

        uint32_t aS = sbase + OFF_A + buf * STG_A;
        uint32_t bS = sbase + OFF_B + buf * STG_B;

        #pragma unroll
        for (int ks = 0; ks < 2; ++ks) {
            const int cb = ks << 1;
            uint32_t a[2][4];
            #pragma unroll
            for (int mt = 0; mt < 2; ++mt)
                ldsm_x4(a[mt], aS + swz(wm * 32 + mt * 16 + a_row, cb + a_ch));
            uint32_t b[8][2];
            #pragma unroll
            for (int b4 = 0; b4 < 4; ++b4) {
                uint32_t r4[4];
                ldsm_x4(r4, bS + swz(wn * 64 + b4 * 16 + b_row, cb + b_ch));
                b[2*b4][0] = r4[0]; b[2*b4][1] = r4[1];
                b[2*b4+1][0] = r4[2]; b[2*b4+1][1] = r4[3];
            }
            #pragma unroll
            for (int mt = 0; mt < 2; ++mt)
                #pragma unroll
                for (int nt = 0; nt < 8; ++nt)
                    mma_u8(acc[mt][nt], a[mt], b[nt][0], b[nt][1]);
        }

        __syncthreads();   // all consumers done with stage (it+NST-1)&3's previous round
        int nx = it + NST - 1;
        if (tid == 0 && nx < NIT) {
            int s = nx & (NST - 1);
            MBAR_EXPECT_TX(mbf + s * 8, 2 * SLAB);
            bulk_cp(sbase + OFF_A + s * STG_A, Abase + (size_t)nx * SLAB, SLAB, mbf + s * 8);
            bulk_cp(sbase + OFF_B + s * STG_B, Bbase + (size_t)nx * SLAB, SLAB, mbf + s * 8);
        }
    }

    // ---------------- Epilogue: integer correction + affine + bias ----------
    const int qrow = lid >> 2;
    const int qcol = (lid & 3) << 1;
    #pragma unroll
    for (int mt = 0; mt < 2; ++mt) {
        const int ml0 = wm * 32 + mt * 16 + qrow;
        const int ra0 = trA[ml0];
        const int ra1 = trA[ml0 + 8];
        float* orow0 = out + (size_t)(tile_m + ml0) * N_DIM + tile_n;
        float* orow1 = orow0 + (size_t)8 * N_DIM;
        #pragma unroll
        for (int nt = 0; nt < 8; ++nt) {
            const int nl = wn * 64 + nt * 8 + qcol;
            const int z0 = tzw[nl], z1 = tzw[nl + 1];
            const int i0 = tin[nl], i1 = tin[nl + 1];
            const float s0 = tsc[nl], s1 = tsc[nl + 1];
            const float g0 = tbs[nl], g1 = tbs[nl + 1];
            float2 v0, v1;
            v0.x = s0 * (float)(acc[mt][nt][0] - z0 * ra0 + i0) + g0;
            v0.y = s1 * (float)(acc[mt][nt][1] - z1 * ra0 + i1) + g1;
            v1.x = s0 * (float)(acc[mt][nt][2] - z0 * ra1 + i0) + g0;
            v1.y = s1 * (float)(acc[mt][nt][3] - z1 * ra1 + i1) + g1;
            *reinterpret_cast<float2*>(orow0 + nl) = v0;
            *reinterpret_cast<float2*>(orow1 + nl) = v1;
        }
    }
}

// ---------------------------------------------------------------------------
// Launch
// ---------------------------------------------------------------------------
extern "C" void kernel_launch(void* const* d_in, const int* in_sizes, int n_in,
                              void* d_out, int out_size)
{
    const float* x       = (const float*)d_in[0];
    const int*   wq      = (const int*)  d_in[1];
    const float* wscale  = (const float*)d_in[2];
    const int*   wzp     = (const int*)  d_in[3];
    const float* ascale  = (const float*)d_in[4];
    const int*   azp     = (const int*)  d_in[5];
    const float* bias    = (const float*)d_in[6];
    float*       out     = (float*)d_out;

    cudaFuncSetAttribute(gemm_imma_kernel,
                         cudaFuncAttributeMaxDynamicSharedMemorySize, SMEM_BYTES);

    quant_x_kernel<<<M_DIM, 256>>>(x, ascale, azp);
    pack_w_kernel<<<N_DIM, 256>>>(wq);

    dim3 grid(N_DIM / BN, M_DIM / BM);   // (32, 64)
    gemm_imma_kernel<<<grid, 256, SMEM_BYTES>>>(wscale, wzp, ascale, azp, bias, out);
}

// round 10
// speedup vs baseline: 2.8755x; 2.6954x over previous
#include <cuda_runtime.h>
#include <cstdint>

// Problem dims (fixed for QuantizedLinear_49246095015985)
#define M_DIM 8192
#define K_DIM 4096
#define N_DIM 4096

// GEMM tiling (bf16): 128x128 CTA tile, k-slab = 32 elements (64B rows)
#define BM 128
#define BN 128
#define BKE 32                  // k elements per slab
#define NST 4                   // pipeline stages
#define NIT (K_DIM / BKE)       // 128 k-slabs

#define SLAB 8192               // 128 rows x 64B, per matrix per slab
#define SLAB_W 2048             // words per slab
#define OFF_A 0
#define OFF_B (NST * SLAB)                   // 32768
#define OFF_EPI (OFF_B + NST * SLAB)         // 65536
#define OFF_MB (OFF_EPI + 1024)              // 4 x 8B full barriers
#define SMEM_BYTES (OFF_MB + 64 + 1024)

// Scratch (device globals: allocation-free rule).
// TILED + PRE-SWIZZLED bf16 layouts:
//   g_Ab = [64 mtiles][128 kslabs][8KB block]  (centered activations, bf16)
//   g_Wb = [32 ntiles][128 kslabs][8KB block]  (centered weights, bf16)
__device__ uint32_t g_Ab[(size_t)M_DIM * K_DIM / 2];   // 64 MB
__device__ uint32_t g_Wb[(size_t)N_DIM * K_DIM / 2];   // 32 MB

// ---------------------------------------------------------------------------
// Helpers
// ---------------------------------------------------------------------------
__device__ __forceinline__ uint32_t cvta_smem(const void* p) {
    return (uint32_t)__cvta_generic_to_shared(p);
}

// Within an 8KB block: row = 64B (4 x 16B chunks), XOR-swizzled chunk position.
__device__ __forceinline__ uint32_t swz(int row, int chunk) {
    return (uint32_t)(row * 64 + ((chunk ^ ((row >> 1) & 3)) << 4));
}

#define MBAR_INIT(addr, cnt) \
    asm volatile("mbarrier.init.shared.b64 [%0], %1;" :: "r"(addr), "r"(cnt) : "memory")

#define MBAR_EXPECT_TX(addr, bytes) \
    asm volatile("mbarrier.arrive.expect_tx.shared.b64 _, [%0], %1;" \
                 :: "r"(addr), "r"(bytes) : "memory")

#define MB_WAIT(addr, ph) do { \
    uint32_t _d_; \
    asm volatile("{\n\t.reg .pred p;\n\t" \
        "mbarrier.try_wait.parity.acquire.cta.shared::cta.b64 p, [%1], %2;\n\t" \
        "selp.b32 %0, 1, 0, p;\n\t}" : "=r"(_d_) : "r"(addr), "r"(ph) : "memory"); \
    while (!_d_) { \
        asm volatile("{\n\t.reg .pred p;\n\t" \
            "mbarrier.try_wait.parity.acquire.cta.shared::cta.b64 p, [%1], %2, 0x989680;\n\t" \
            "selp.b32 %0, 1, 0, p;\n\t}" : "=r"(_d_) : "r"(addr), "r"(ph) : "memory"); \
    } \
} while (0)

__device__ __forceinline__ void bulk_cp(uint32_t dst, const void* src,
                                        uint32_t bytes, uint32_t mbar) {
    asm volatile(
        "cp.async.bulk.shared::cluster.global.mbarrier::complete_tx::bytes "
        "[%0], [%1], %2, [%3];"
        :: "r"(dst), "l"(src), "r"(bytes), "r"(mbar) : "memory");
}

__device__ __forceinline__ void ldsm_x4(uint32_t (&r)[4], uint32_t addr) {
    asm volatile("ldmatrix.sync.aligned.m8n8.x4.shared.b16 {%0,%1,%2,%3}, [%4];"
                 : "=r"(r[0]), "=r"(r[1]), "=r"(r[2]), "=r"(r[3]) : "r"(addr));
}

__device__ __forceinline__ void mma_bf16(float (&c)[4], const uint32_t (&a)[4],
                                         uint32_t b0, uint32_t b1) {
    asm volatile(
        "mma.sync.aligned.m16n8k16.row.col.f32.bf16.bf16.f32 "
        "{%0,%1,%2,%3}, {%4,%5,%6,%7}, {%8,%9}, {%0,%1,%2,%3};"
        : "+f"(c[0]), "+f"(c[1]), "+f"(c[2]), "+f"(c[3])
        : "r"(a[0]), "r"(a[1]), "r"(a[2]), "r"(a[3]), "r"(b0), "r"(b1));
}

// pack two floats into bf16x2 word: low half = lo, high half = hi
__device__ __forceinline__ uint32_t pack_bf16x2(float lo, float hi) {
    uint32_t r;
    asm("cvt.rn.bf16x2.f32 %0, %1, %2;" : "=r"(r) : "f"(hi), "f"(lo));
    return r;
}

// ---------------------------------------------------------------------------
// Kernel 1: quantize + center activations -> bf16, tiled+swizzled layout.
// One block per row (8192), 256 threads; thread t handles k = t*16 .. t*16+15.
// ---------------------------------------------------------------------------
__global__ void quant_x_kernel(const float* __restrict__ x,
                               const float* __restrict__ act_scale,
                               const int* __restrict__ act_zp)
{
    const int row = blockIdx.x;
    const int mtile = row >> 7, r = row & 127;
    const float s   = act_scale[0];
    const float zpf = (float)act_zp[0];
    const int tid = threadIdx.x;

    const int kslab = tid >> 1;             // 0..127
    const int g0 = (tid & 1) << 1;          // chunk pair within slab: 0 or 2
    const float4* xr = reinterpret_cast<const float4*>(x + (size_t)row * K_DIM + kslab * BKE + g0 * 8);

    size_t base = ((size_t)(mtile * NIT + kslab)) * SLAB_W;
    #pragma unroll
    for (int c = 0; c < 2; ++c) {           // two 16B chunks (8 bf16 each)
        float4 v0 = xr[c * 2 + 0];
        float4 v1 = xr[c * 2 + 1];
        float q[8] = {v0.x, v0.y, v0.z, v0.w, v1.x, v1.y, v1.z, v1.w};
        #pragma unroll
        for (int e = 0; e < 8; ++e)
            q[e] = fminf(fmaxf(rintf(__fdiv_rn(q[e], s)) + zpf, 0.f), 255.f) - zpf;
        uint4 w;
        w.x = pack_bf16x2(q[0], q[1]);
        w.y = pack_bf16x2(q[2], q[3]);
        w.z = pack_bf16x2(q[4], q[5]);
        w.w = pack_bf16x2(q[6], q[7]);
        int chunk = g0 + c;
        uint32_t woff = (uint32_t)(r * 16 + ((chunk ^ ((r >> 1) & 3)) << 2));
        *reinterpret_cast<uint4*>(&g_Ab[base + woff]) = w;
    }
}

// ---------------------------------------------------------------------------
// Kernel 2: center weights -> bf16, tiled+swizzled layout.
// ---------------------------------------------------------------------------
__global__ void pack_w_kernel(const int* __restrict__ wq,
                              const int* __restrict__ wzp)
{
    const int row = blockIdx.x;
    const int ntile = row >> 7, r = row & 127;
    const float zw = (float)wzp[row];
    const int tid = threadIdx.x;

    const int kslab = tid >> 1;
    const int g0 = (tid & 1) << 1;
    const int4* wr = reinterpret_cast<const int4*>(wq + (size_t)row * K_DIM + kslab * BKE + g0 * 8);

    size_t base = ((size_t)(ntile * NIT + kslab)) * SLAB_W;
    #pragma unroll
    for (int c = 0; c < 2; ++c) {
        int4 v0 = wr[c * 2 + 0];
        int4 v1 = wr[c * 2 + 1];
        float q[8] = {(float)v0.x, (float)v0.y, (float)v0.z, (float)v0.w,
                      (float)v1.x, (float)v1.y, (float)v1.z, (float)v1.w};
        #pragma unroll
        for (int e = 0; e < 8; ++e) q[e] -= zw;
        uint4 w;
        w.x = pack_bf16x2(q[0], q[1]);
        w.y = pack_bf16x2(q[2], q[3]);
        w.z = pack_bf16x2(q[4], q[5]);
        w.w = pack_bf16x2(q[6], q[7]);
        int chunk = g0 + c;
        uint32_t woff = (uint32_t)(r * 16 + ((chunk ^ ((r >> 1) & 3)) << 2));
        *reinterpret_cast<uint4*>(&g_Wb[base + woff]) = w;
    }
}

// ---------------------------------------------------------------------------
// Kernel 3: bf16 HMMA GEMM, 128x128 CTA tile, 8 warps (4x2), warp tile 32x64.
// 4-stage ring fed by cp.async.bulk. Epilogue: out = sa*ws[o]*acc + bias[o].
// ---------------------------------------------------------------------------
__global__ __launch_bounds__(256, 2)
void gemm_hmma_kernel(const float* __restrict__ wscale,
                      const float* __restrict__ ascale,
                      const float* __restrict__ bias,
                      float*       __restrict__ out)
{
    extern __shared__ __align__(1024) uint8_t smem_raw[];
    uint32_t raw = cvta_smem(smem_raw);
    uint32_t sbase = (raw + 1023u) & ~1023u;
    uint8_t* smem_gen = smem_raw + (sbase - raw);

    const int tid = threadIdx.x;
    const int wid = tid >> 5;
    const int lid = tid & 31;
    const int wm  = wid & 3;        // warp row (32 rows each)
    const int wn  = wid >> 2;       // warp col (64 cols each)
    const int tile_m = blockIdx.y << 7;
    const int tile_n = blockIdx.x << 7;

    const uint8_t* Abase = reinterpret_cast<const uint8_t*>(g_Ab)
                         + (size_t)blockIdx.y * NIT * SLAB;
    const uint8_t* Bbase = reinterpret_cast<const uint8_t*>(g_Wb)
                         + (size_t)blockIdx.x * NIT * SLAB;
    const uint32_t mbf = sbase + OFF_MB;

    if (tid == 0) {
        #pragma unroll
        for (int s = 0; s < NST; ++s) MBAR_INIT(mbf + s * 8, 1);
        asm volatile("fence.proxy.async.shared::cta;" ::: "memory");
    }

    // Epilogue constants
    float* tsc = reinterpret_cast<float*>(smem_gen + OFF_EPI);
    float* tbs = reinterpret_cast<float*>(smem_gen + OFF_EPI + 512);
    if (tid >= 128) {
        const float sa = ascale[0];
        int n = tid - 128;
        int o = tile_n + n;
        tsc[n] = sa * wscale[o];
        tbs[n] = bias[o];
    }
    __syncthreads();

    // Prologue: fill NST-1 stages
    if (tid == 0) {
        #pragma unroll
        for (int s = 0; s < NST - 1; ++s) {
            MBAR_EXPECT_TX(mbf + s * 8, 2 * SLAB);
            bulk_cp(sbase + OFF_A + s * SLAB, Abase + (size_t)s * SLAB, SLAB, mbf + s * 8);
            bulk_cp(sbase + OFF_B + s * SLAB, Bbase + (size_t)s * SLAB, SLAB, mbf + s * 8);
        }
    }

    float acc[2][8][4];
    #pragma unroll
    for (int mt = 0; mt < 2; ++mt)
        #pragma unroll
        for (int nt = 0; nt < 8; ++nt)
            #pragma unroll
            for (int q = 0; q < 4; ++q) acc[mt][nt][q] = 0.f;

    // ldmatrix lane geometry (chunk = 16B = 8 bf16 = k8)
    const int a_row = (lid & 7) + ((lid >> 3) & 1) * 8;
    const int a_ch  = (lid >> 4);
    const int b_row = (lid & 7) + (lid >> 4) * 8;
    const int b_ch  = ((lid >> 3) & 1);

    int pf[NST] = {0, 0, 0, 0};

    for (int it = 0; it < NIT; ++it) {
        int buf = it & (NST - 1);
        MB_WAIT(mbf + buf * 8, pf[buf]); pf[buf] ^= 1;

        uint32_t aS = sbase + OFF_A + buf * SLAB;
        uint32_t bS = sbase + OFF_B + buf * SLAB;

        #pragma unroll
        for (int ks = 0; ks < 2; ++ks) {           // two k16 steps per slab
            const int cb = ks << 1;
            uint32_t a[2][4];
            #pragma unroll
            for (int mt = 0; mt < 2; ++mt)
                ldsm_x4(a[mt], aS + swz(wm * 32 + mt * 16 + a_row, cb + a_ch));
            uint32_t b[8][2];
            #pragma unroll
            for (int b4 = 0; b4 < 4; ++b4) {
                uint32_t r4[4];
                ldsm_x4(r4, bS + swz(wn * 64 + b4 * 16 + b_row, cb + b_ch));
                b[2*b4][0] = r4[0]; b[2*b4][1] = r4[1];
                b[2*b4+1][0] = r4[2]; b[2*b4+1][1] = r4[3];
            }
            #pragma unroll
            for (int mt = 0; mt < 2; ++mt)
                #pragma unroll
                for (int nt = 0; nt < 8; ++nt)
                    mma_bf16(acc[mt][nt], a[mt], b[nt][0], b[nt][1]);
        }

        __syncthreads();
        int nx = it + NST - 1;
        if (tid == 0 && nx < NIT) {
            int s = nx & (NST - 1);
            MBAR_EXPECT_TX(mbf + s * 8, 2 * SLAB);
            bulk_cp(sbase + OFF_A + s * SLAB, Abase + (size_t)nx * SLAB, SLAB, mbf + s * 8);
            bulk_cp(sbase + OFF_B + s * SLAB, Bbase + (size_t)nx * SLAB, SLAB, mbf + s * 8);
        }
    }

    // ---------------- Epilogue: out = tsc[n]*acc + tbs[n] -------------------
    const int qrow = lid >> 2;
    const int qcol = (lid & 3) << 1;
    #pragma unroll
    for (int mt = 0; mt < 2; ++mt) {
        const int ml0 = wm * 32 + mt * 16 + qrow;
        float* orow0 = out + (size_t)(tile_m + ml0) * N_DIM + tile_n;
        float* orow1 = orow0 + (size_t)8 * N_DIM;
        #pragma unroll
        for (int nt = 0; nt < 8; ++nt) {
            const int nl = wn * 64 + nt * 8 + qcol;
            const float s0 = tsc[nl], s1 = tsc[nl + 1];
            const float g0 = tbs[nl], g1 = tbs[nl + 1];
            float2 v0, v1;
            v0.x = s0 * acc[mt][nt][0] + g0;
            v0.y = s1 * acc[mt][nt][1] + g1;
            v1.x = s0 * acc[mt][nt][2] + g0;
            v1.y = s1 * acc[mt][nt][3] + g1;
            *reinterpret_cast<float2*>(orow0 + nl) = v0;
            *reinterpret_cast<float2*>(orow1 + nl) = v1;
        }
    }
}

// ---------------------------------------------------------------------------
// Launch
// ---------------------------------------------------------------------------
extern "C" void kernel_launch(void* const* d_in, const int* in_sizes, int n_in,
                              void* d_out, int out_size)
{
    const float* x       = (const float*)d_in[0];
    const int*   wq      = (const int*)  d_in[1];
    const float* wscale  = (const float*)d_in[2];
    const int*   wzp     = (const int*)  d_in[3];
    const float* ascale  = (const float*)d_in[4];
    const int*   azp     = (const int*)  d_in[5];
    const float* bias    = (const float*)d_in[6];
    float*       out     = (float*)d_out;

    cudaFuncSetAttribute(gemm_hmma_kernel,
                         cudaFuncAttributeMaxDynamicSharedMemorySize, SMEM_BYTES);

    quant_x_kernel<<<M_DIM, 256>>>(x, ascale, azp);
    pack_w_kernel<<<N_DIM, 256>>>(wq, wzp);

    dim3 grid(N_DIM / BN, M_DIM / BM);   // (32, 64)
    gemm_hmma_kernel<<<grid, 256, SMEM_BYTES>>>(wscale, ascale, bias, out);
}